// round 15
// baseline (speedup 1.0000x reference)
#include <cuda_runtime.h>
#include <cuda_bf16.h>
#include <math.h>
#include <stdint.h>

#define B_    4096
#define IN_   1024
#define HID_  4096
#define OUT_  1024
#define E_    8
#define EH_   (E_ * HID_)

// mma-GEMM tiling
#define KCH   32                 // k per chunk
#define RSB   80                 // smem row stride bytes (64B data + 16 pad)
#define TILEB (128 * RSB)        // 10240 B per matrix tile
#define BUFB  (4 * TILEB)        // Ahi,Alo,Bhi,Blo = 40960 B per buffer

// ---------------- scratch (allocation-free rule) ----------------
__device__ float d_Hg[(size_t)B_ * HID_];
__device__ float d_probs[B_ * E_];
__device__ float d_gate[B_ * E_];
__device__ __nv_bfloat16 d_xhi[(size_t)B_ * IN_];
__device__ __nv_bfloat16 d_xlo[(size_t)B_ * IN_];
__device__ __nv_bfloat16 d_w1thi[(size_t)EH_ * IN_];
__device__ __nv_bfloat16 d_w1tlo[(size_t)EH_ * IN_];
__device__ __nv_bfloat16 d_w2thi[(size_t)OUT_ * EH_];
__device__ __nv_bfloat16 d_w2tlo[(size_t)OUT_ * EH_];
__device__ __nv_bfloat16 d_Hhi[(size_t)B_ * EH_];
__device__ __nv_bfloat16 d_Hlo[(size_t)B_ * EH_];

// streams/events for forked graph capture (created once at load; no device mem)
static cudaStream_t g_s2;
static cudaEvent_t  g_evFork, g_evJoin;
static struct GInit {
    GInit() {
        cudaStreamCreateWithFlags(&g_s2, cudaStreamNonBlocking);
        cudaEventCreateWithFlags(&g_evFork, cudaEventDisableTiming);
        cudaEventCreateWithFlags(&g_evJoin, cudaEventDisableTiming);
    }
} g_init;

__device__ __forceinline__ uint32_t smem_u32(const void* p) {
    uint32_t a;
    asm("{ .reg .u64 t; cvta.to.shared.u64 t, %1; cvt.u32.u64 %0, t; }" : "=r"(a) : "l"(p));
    return a;
}
#define LDSM4(r, addr) \
    asm volatile("ldmatrix.sync.aligned.m8n8.x4.shared.b16 {%0,%1,%2,%3}, [%4];" \
        : "=r"((r)[0]), "=r"((r)[1]), "=r"((r)[2]), "=r"((r)[3]) : "r"(addr))
#define MMA_BF16(c, a, b0, b1) \
    asm volatile("mma.sync.aligned.m16n8k16.row.col.f32.bf16.bf16.f32 " \
        "{%0,%1,%2,%3}, {%4,%5,%6,%7}, {%8,%9}, {%0,%1,%2,%3};" \
        : "+f"((c)[0]), "+f"((c)[1]), "+f"((c)[2]), "+f"((c)[3]) \
        : "r"((a)[0]), "r"((a)[1]), "r"((a)[2]), "r"((a)[3]), "r"(b0), "r"(b1))
#define CPA16(dst, src) \
    asm volatile("cp.async.cg.shared.global [%0], [%1], 16;" :: "r"(dst), "l"(src))
#define CPA_COMMIT() asm volatile("cp.async.commit_group;" ::: "memory")
#define CPA_WAIT1()  asm volatile("cp.async.wait_group 1;" ::: "memory")
#define CPA_WAIT0()  asm volatile("cp.async.wait_group 0;" ::: "memory")

__device__ __forceinline__ uint32_t pk(__nv_bfloat16 a, __nv_bfloat16 b) {
    return (uint32_t)__bfloat16_as_ushort(a) | ((uint32_t)__bfloat16_as_ushort(b) << 16);
}

// ===========================================================================
// GATING PATH — value-exact vs reference. DO NOT CHANGE ARITHMETIC ORDER.
// ===========================================================================
__device__ __forceinline__ float xla_expf(float input)
{
    float x = fminf(fmaxf(input, -88.3762626647949f), 88.3762626647950f);
    float fx = floorf(__fadd_rn(__fmul_rn(x, 1.44269504088896341f), 0.5f));
    float tmp = __fmul_rn(0.693359375f, fx);
    float z   = __fmul_rn(-2.12194440e-4f, fx);
    float xr  = __fsub_rn(x, tmp);
    xr = __fsub_rn(xr, z);
    z  = __fmul_rn(xr, xr);
    float y = __fadd_rn(__fmul_rn(xr, 1.9875691500E-4f), 1.3981999507E-3f);
    y = __fadd_rn(__fmul_rn(y, xr), 8.3334519073E-3f);
    y = __fadd_rn(__fmul_rn(y, xr), 4.1665795894E-2f);
    y = __fadd_rn(__fmul_rn(y, xr), 1.6666665459E-1f);
    y = __fadd_rn(__fmul_rn(y, xr), 5.0000001201E-1f);
    y = __fadd_rn(__fmul_rn(y, z), xr);
    y = __fadd_rn(1.0f, y);
    int n = (int)fx;
    float p2n = __int_as_float((n + 127) << 23);
    return fmaxf(__fmul_rn(y, p2n), input);
}

// Unfused MAC (value-exact): t = rn(a*b); acc = rn(t*1.0 + acc).
__device__ __forceinline__ void mm_step16_uf(const float (*As)[132], const float (*Bs)[132],
                                             float acc[8][8], int tm, int tn)
{
#pragma unroll
    for (int k = 0; k < 16; k++) {
        float a[8], b[8];
        *(float4*)&a[0] = *(const float4*)&As[k][tm];
        *(float4*)&a[4] = *(const float4*)&As[k][tm + 4];
        *(float4*)&b[0] = *(const float4*)&Bs[k][tn];
        *(float4*)&b[4] = *(const float4*)&Bs[k][tn + 4];
#pragma unroll
        for (int i = 0; i < 8; i++)
#pragma unroll
            for (int j = 0; j < 8; j++) {
                float t = __fmul_rn(a[i], b[j]);
                asm volatile("fma.rn.f32 %0, %1, 0f3F800000, %0;"
                             : "+f"(acc[i][j]) : "f"(t));
            }
    }
}

__global__ void __launch_bounds__(256, 2)
hg_gemm(const float* __restrict__ A, const float* __restrict__ W,
        const float* __restrict__ bias, float* __restrict__ C)
{
    const int bm = blockIdx.y * 128, bn = blockIdx.x * 128, tid = threadIdx.x;
    const int N = HID_, K = IN_;

    __shared__ __align__(16) float As[2][16][132];
    __shared__ __align__(16) float Bs[2][16][132];

    const int a_row = tid >> 2, a_col = (tid & 3) << 2;
    const int b_row = tid >> 5, b_col = (tid & 31) << 2;
    const int tm = (tid >> 4) << 3, tn = (tid & 15) << 3;

    float acc[8][8];
#pragma unroll
    for (int i = 0; i < 8; i++)
#pragma unroll
        for (int j = 0; j < 8; j++) acc[i][j] = 0.f;

    const float* Ab = A + (size_t)bm * K;
    float4 pa0, pa1, pb0, pb1;
    pa0 = *(const float4*)(Ab + (size_t)a_row * K + a_col);
    pa1 = *(const float4*)(Ab + (size_t)(a_row + 64) * K + a_col);
    pb0 = *(const float4*)(W + (size_t)b_row * N + bn + b_col);
    pb1 = *(const float4*)(W + (size_t)(b_row + 8) * N + bn + b_col);

    int buf = 0;
    As[buf][a_col+0][a_row] = pa0.x; As[buf][a_col+1][a_row] = pa0.y;
    As[buf][a_col+2][a_row] = pa0.z; As[buf][a_col+3][a_row] = pa0.w;
    As[buf][a_col+0][a_row+64] = pa1.x; As[buf][a_col+1][a_row+64] = pa1.y;
    As[buf][a_col+2][a_row+64] = pa1.z; As[buf][a_col+3][a_row+64] = pa1.w;
    *(float4*)&Bs[buf][b_row][b_col]   = pb0;
    *(float4*)&Bs[buf][b_row+8][b_col] = pb1;
    __syncthreads();

    for (int kt = 16; kt < K; kt += 16) {
        pa0 = *(const float4*)(Ab + (size_t)a_row * K + kt + a_col);
        pa1 = *(const float4*)(Ab + (size_t)(a_row + 64) * K + kt + a_col);
        pb0 = *(const float4*)(W + (size_t)(kt + b_row) * N + bn + b_col);
        pb1 = *(const float4*)(W + (size_t)(kt + b_row + 8) * N + bn + b_col);
        mm_step16_uf(As[buf], Bs[buf], acc, tm, tn);
        buf ^= 1;
        As[buf][a_col+0][a_row] = pa0.x; As[buf][a_col+1][a_row] = pa0.y;
        As[buf][a_col+2][a_row] = pa0.z; As[buf][a_col+3][a_row] = pa0.w;
        As[buf][a_col+0][a_row+64] = pa1.x; As[buf][a_col+1][a_row+64] = pa1.y;
        As[buf][a_col+2][a_row+64] = pa1.z; As[buf][a_col+3][a_row+64] = pa1.w;
        *(float4*)&Bs[buf][b_row][b_col]   = pb0;
        *(float4*)&Bs[buf][b_row+8][b_col] = pb1;
        __syncthreads();
    }
    mm_step16_uf(As[buf], Bs[buf], acc, tm, tn);

#pragma unroll
    for (int i = 0; i < 8; i++) {
        const int row = bm + tm + i;
        float o[8];
#pragma unroll
        for (int j = 0; j < 8; j++) {
            float v = __fadd_rn(acc[i][j], bias[bn + tn + j]);
            o[j] = fmaxf(v, 0.f);
        }
        *(float4*)&C[(size_t)row * N + bn + tn]     = *(float4*)&o[0];
        *(float4*)&C[(size_t)row * N + bn + tn + 4] = *(float4*)&o[4];
    }
}

__global__ void __launch_bounds__(256)
gating_logits_softmax(const float* __restrict__ Hg, const float* __restrict__ gW2,
                      const float* __restrict__ gb2, float* __restrict__ probs)
{
    const int t = blockIdx.x * blockDim.x + threadIdx.x;
    const int b = t >> 3, e = t & 7;
    const float* h = Hg + (size_t)b * HID_;
    const float* w = gW2 + e;

    float acc = 0.f;
#pragma unroll 8
    for (int k = 0; k < HID_; k++)
        acc = __fadd_rn(acc, __fmul_rn(h[k], w[k * 8]));
    float lg = __fadd_rn(acc, gb2[e]);

    const int lane = threadIdx.x & 31;
    const int base = lane & ~7;
    float l[8];
#pragma unroll
    for (int i = 0; i < 8; i++) l[i] = __shfl_sync(0xffffffffu, lg, base + i);

    float mx = l[0];
#pragma unroll
    for (int i = 1; i < 8; i++) mx = fmaxf(mx, l[i]);
    float ex[8], sum = 0.f;
#pragma unroll
    for (int i = 0; i < 8; i++) {
        ex[i] = xla_expf(__fsub_rn(l[i], mx));
        sum = __fadd_rn(sum, ex[i]);
    }
    probs[t] = __fdiv_rn(ex[e], sum);
}

__global__ void gating_scan(const float* __restrict__ probs,
                            float* __restrict__ gate, float* __restrict__ gout)
{
    __shared__ __align__(16) float sp[1024 * 8];
    __shared__ int s_allzero;
    const int tid = threadIdx.x;

    float rta[8];
#pragma unroll
    for (int e = 0; e < 8; e++) rta[e] = 0.f;
    bool anynz = false;

    for (int c0 = 0; c0 < B_; c0 += 1024) {
        for (int i = tid; i < 2048; i += 256)
            *(float4*)&sp[i * 4] = *(const float4*)&probs[(size_t)c0 * 8 + i * 4];
        __syncthreads();

        if (tid == 0) {
            for (int r = 0; r < 1024; r++) {
                float s[8], rta1[8];
                *(float4*)&s[0] = *(const float4*)&sp[r * 8];
                *(float4*)&s[4] = *(const float4*)&sp[r * 8 + 4];
#pragma unroll
                for (int e = 0; e < 8; e++) rta1[e] = __fadd_rn(rta[e], s[e]);

                float ssum = 0.f;
#pragma unroll
                for (int e = 0; e < 8; e++) ssum = __fadd_rn(ssum, rta1[e]);
                const float thr = __fadd_rn(__fdiv_rn(ssum, 8.0f), 0.1f);

                bool any = false, m[8];
#pragma unroll
                for (int e = 0; e < 8; e++) { m[e] = rta1[e] > thr; any |= m[e]; }

                float mod[8];
#pragma unroll
                for (int e = 0; e < 8; e++) mod[e] = m[e] ? 0.f : s[e];
                float norm = 0.f;
#pragma unroll
                for (int e = 0; e < 8; e++) norm = __fadd_rn(norm, mod[e]);
                const float denom = (norm == 0.f) ? 1.f : norm;
#pragma unroll
                for (int e = 0; e < 8; e++) mod[e] = __fdiv_rn(mod[e], denom);

#pragma unroll
                for (int e = 0; e < 8; e++) {
                    const float rta2 = any ? __fsub_rn(rta1[e], s[e]) : rta1[e];
                    rta[e] = __fadd_rn(rta2, mod[e]);
                }
                anynz |= (norm > 0.f);

                const int row = c0 + r;
                float4 m0 = make_float4(mod[0], mod[1], mod[2], mod[3]);
                float4 m1 = make_float4(mod[4], mod[5], mod[6], mod[7]);
                *(float4*)&gate[(size_t)row * 8]     = m0;
                *(float4*)&gate[(size_t)row * 8 + 4] = m1;
                *(float4*)&gout[(size_t)row * 8]     = m0;
                *(float4*)&gout[(size_t)row * 8 + 4] = m1;
            }
            if (c0 + 1024 >= B_) s_allzero = anynz ? 0 : 1;
        }
        __syncthreads();
    }

    if (s_allzero) {
        for (int i = tid; i < B_ * E_; i += 256) { gate[i] = 1.f / E_; gout[i] = 1.f / E_; }
    }
}

// ===========================================================================
// EXPERT PATH — mma.sync bf16 3-pass split; GEMM1 gate-free, gate folded
// into GEMM2 per-expert accumulators.
// ===========================================================================

__global__ void __launch_bounds__(256)
split_x(const float* __restrict__ x, __nv_bfloat16* __restrict__ hi,
        __nv_bfloat16* __restrict__ lo, int n)
{
    int i = blockIdx.x * 256 + threadIdx.x;
    if (i < n) {
        float v = x[i];
        __nv_bfloat16 h = __float2bfloat16(v);
        hi[i] = h;
        lo[i] = __float2bfloat16(v - __bfloat162float(h));
    }
}

__global__ void transpose_split(const float* __restrict__ in,
                                __nv_bfloat16* __restrict__ ohi,
                                __nv_bfloat16* __restrict__ olo, int R, int C)
{
    __shared__ float t[32][33];
    const size_t base = (size_t)blockIdx.z * R * C;
    const int c0 = blockIdx.x * 32, r0 = blockIdx.y * 32;
    const int tx = threadIdx.x, ty = threadIdx.y;   // 32 x 8
#pragma unroll
    for (int i = 0; i < 32; i += 8)
        t[ty + i][tx] = in[base + (size_t)(r0 + ty + i) * C + c0 + tx];
    __syncthreads();
#pragma unroll
    for (int i = 0; i < 32; i += 8) {
        float v = t[tx][ty + i];
        __nv_bfloat16 h = __float2bfloat16(v);
        size_t o = base + (size_t)(c0 + ty + i) * R + r0 + tx;
        ohi[o] = h;
        olo[o] = __float2bfloat16(v - __bfloat162float(h));
    }
}

// GEMM1 (no gate): H'hi/lo = split(relu(x@eW1[e] + eb1)). Independent of gating.
__global__ void __launch_bounds__(256, 2)
mma_gemm1(const __nv_bfloat16* __restrict__ Ahi, const __nv_bfloat16* __restrict__ Alo,
          const __nv_bfloat16* __restrict__ Bhi, const __nv_bfloat16* __restrict__ Blo,
          const float* __restrict__ bias,
          __nv_bfloat16* __restrict__ outhi, __nv_bfloat16* __restrict__ outlo,
          int K, int NC)
{
    extern __shared__ char smem[];
    const uint32_t sbase = smem_u32(smem);
    const int tid = threadIdx.x, wid = tid >> 5, lane = tid & 31;
    const int bm = blockIdx.x * 128;
    const int bn = blockIdx.y * 128;
    const int m0 = (wid & 3) * 32;
    const int n0 = (wid >> 2) * 64;

    float acc[2][8][4];
#pragma unroll
    for (int i = 0; i < 2; i++)
#pragma unroll
        for (int j = 0; j < 8; j++)
#pragma unroll
            for (int q = 0; q < 4; q++) acc[i][j][q] = 0.f;

    const int r0 = tid >> 2, q4 = tid & 3;
    const __nv_bfloat16* tiles[4] = { Ahi, Alo, Bhi, Blo };

    auto issue = [&](int c, int buf) {
        const int kc = c * KCH;
#pragma unroll
        for (int j = 0; j < 8; j++) {
            const int tle = j >> 1;
            const int rb  = (tle < 2) ? bm : bn;
            const int r   = ((j & 1) ? 64 : 0) + r0;
            const __nv_bfloat16* src = tiles[tle] + (size_t)(rb + r) * K + kc + q4 * 8;
            const uint32_t dst = sbase + (uint32_t)(buf * BUFB + tle * TILEB + r * RSB + q4 * 16);
            CPA16(dst, src);
        }
        CPA_COMMIT();
    };

    issue(0, 0);

    for (int c = 0; c < NC; c++) {
        const int cur = c & 1;
        if (c + 1 < NC) { issue(c + 1, cur ^ 1); CPA_WAIT1(); }
        else            { CPA_WAIT0(); }
        __syncthreads();

        const uint32_t sA_h = sbase + (uint32_t)(cur * BUFB);
        const uint32_t sA_l = sA_h + TILEB;
        const uint32_t sB_h = sA_h + 2 * TILEB;
        const uint32_t sB_l = sA_h + 3 * TILEB;

#pragma unroll
        for (int ks = 0; ks < KCH / 16; ks++) {
            uint32_t ah[2][4], al[2][4];
            const int ar = lane & 15;
            const int ac = ks * 16 + (lane >> 4) * 8;
#pragma unroll
            for (int mf = 0; mf < 2; mf++) {
                const uint32_t off = (uint32_t)((m0 + mf * 16 + ar) * RSB + ac * 2);
                LDSM4(ah[mf], sA_h + off);
                LDSM4(al[mf], sA_l + off);
            }
            const int br = (lane & 7) + ((lane >> 4) & 1) * 8;
            const int bc = ks * 16 + ((lane >> 3) & 1) * 8;
#pragma unroll
            for (int nf = 0; nf < 4; nf++) {
                uint32_t bh[4], bl[4];
                const uint32_t off = (uint32_t)((n0 + nf * 16 + br) * RSB + bc * 2);
                LDSM4(bh, sB_h + off);
                LDSM4(bl, sB_l + off);
#pragma unroll
                for (int h = 0; h < 2; h++) {
                    const int nn = nf * 2 + h;
                    MMA_BF16(acc[0][nn], ah[0], bh[h*2], bh[h*2+1]);
                    MMA_BF16(acc[0][nn], ah[0], bl[h*2], bl[h*2+1]);
                    MMA_BF16(acc[0][nn], al[0], bh[h*2], bh[h*2+1]);
                    MMA_BF16(acc[1][nn], ah[1], bh[h*2], bh[h*2+1]);
                    MMA_BF16(acc[1][nn], ah[1], bl[h*2], bl[h*2+1]);
                    MMA_BF16(acc[1][nn], al[1], bh[h*2], bh[h*2+1]);
                }
            }
        }
        __syncthreads();
    }

#pragma unroll
    for (int mf = 0; mf < 2; mf++) {
        const int ra = bm + m0 + mf * 16 + (lane >> 2);
        const int rb = ra + 8;
#pragma unroll
        for (int nn = 0; nn < 8; nn++) {
            const int gc = bn + n0 + nn * 8 + (lane & 3) * 2;
            const float b0 = bias[gc], b1 = bias[gc + 1];
            float v00 = fmaxf(acc[mf][nn][0] + b0, 0.f);
            float v01 = fmaxf(acc[mf][nn][1] + b1, 0.f);
            float v10 = fmaxf(acc[mf][nn][2] + b0, 0.f);
            float v11 = fmaxf(acc[mf][nn][3] + b1, 0.f);
            __nv_bfloat16 h00 = __float2bfloat16(v00), h01 = __float2bfloat16(v01);
            __nv_bfloat16 h10 = __float2bfloat16(v10), h11 = __float2bfloat16(v11);
            __nv_bfloat16 l00 = __float2bfloat16(v00 - __bfloat162float(h00));
            __nv_bfloat16 l01 = __float2bfloat16(v01 - __bfloat162float(h01));
            __nv_bfloat16 l10 = __float2bfloat16(v10 - __bfloat162float(h10));
            __nv_bfloat16 l11 = __float2bfloat16(v11 - __bfloat162float(h11));
            *reinterpret_cast<uint32_t*>(&outhi[(size_t)ra * EH_ + gc]) = pk(h00, h01);
            *reinterpret_cast<uint32_t*>(&outhi[(size_t)rb * EH_ + gc]) = pk(h10, h11);
            *reinterpret_cast<uint32_t*>(&outlo[(size_t)ra * EH_ + gc]) = pk(l00, l01);
            *reinterpret_cast<uint32_t*>(&outlo[(size_t)rb * EH_ + gc]) = pk(l10, l11);
        }
    }
}

// GEMM2 with gate folded per expert: out = sum_e g[b,e]*(sum_{k in e} H'W2) + sum_e g*eb2.
#define ECHUNKS 128   // (HID_/KCH) chunks per expert
__global__ void __launch_bounds__(256)
mma_gemm2(const __nv_bfloat16* __restrict__ Ahi, const __nv_bfloat16* __restrict__ Alo,
          const __nv_bfloat16* __restrict__ Bhi, const __nv_bfloat16* __restrict__ Blo,
          const float* __restrict__ eb2, const float* __restrict__ gate,
          float* __restrict__ outf, int K, int NC)
{
    extern __shared__ char smem[];
    const uint32_t sbase = smem_u32(smem);
    const int tid = threadIdx.x, wid = tid >> 5, lane = tid & 31;
    const int bm = blockIdx.x * 128;
    const int bn = blockIdx.y * 128;
    const int m0 = (wid & 3) * 32;
    const int n0 = (wid >> 2) * 64;

    float acc[2][8][4], accF[2][8][4];
#pragma unroll
    for (int i = 0; i < 2; i++)
#pragma unroll
        for (int j = 0; j < 8; j++)
#pragma unroll
            for (int q = 0; q < 4; q++) { acc[i][j][q] = 0.f; accF[i][j][q] = 0.f; }

    const int r0 = tid >> 2, q4 = tid & 3;
    const __nv_bfloat16* tiles[4] = { Ahi, Alo, Bhi, Blo };

    auto issue = [&](int c, int buf) {
        const int kc = c * KCH;
#pragma unroll
        for (int j = 0; j < 8; j++) {
            const int tle = j >> 1;
            const int rb  = (tle < 2) ? bm : bn;
            const int r   = ((j & 1) ? 64 : 0) + r0;
            const __nv_bfloat16* src = tiles[tle] + (size_t)(rb + r) * K + kc + q4 * 8;
            const uint32_t dst = sbase + (uint32_t)(buf * BUFB + tle * TILEB + r * RSB + q4 * 16);
            CPA16(dst, src);
        }
        CPA_COMMIT();
    };

    issue(0, 0);

    for (int c = 0; c < NC; c++) {
        const int cur = c & 1;
        if (c + 1 < NC) { issue(c + 1, cur ^ 1); CPA_WAIT1(); }
        else            { CPA_WAIT0(); }
        __syncthreads();

        const uint32_t sA_h = sbase + (uint32_t)(cur * BUFB);
        const uint32_t sA_l = sA_h + TILEB;
        const uint32_t sB_h = sA_h + 2 * TILEB;
        const uint32_t sB_l = sA_h + 3 * TILEB;

#pragma unroll
        for (int ks = 0; ks < KCH / 16; ks++) {
            uint32_t ah[2][4], al[2][4];
            const int ar = lane & 15;
            const int ac = ks * 16 + (lane >> 4) * 8;
#pragma unroll
            for (int mf = 0; mf < 2; mf++) {
                const uint32_t off = (uint32_t)((m0 + mf * 16 + ar) * RSB + ac * 2);
                LDSM4(ah[mf], sA_h + off);
                LDSM4(al[mf], sA_l + off);
            }
            const int br = (lane & 7) + ((lane >> 4) & 1) * 8;
            const int bc = ks * 16 + ((lane >> 3) & 1) * 8;
#pragma unroll
            for (int nf = 0; nf < 4; nf++) {
                uint32_t bh[4], bl[4];
                const uint32_t off = (uint32_t)((n0 + nf * 16 + br) * RSB + bc * 2);
                LDSM4(bh, sB_h + off);
                LDSM4(bl, sB_l + off);
#pragma unroll
                for (int h = 0; h < 2; h++) {
                    const int nn = nf * 2 + h;
                    MMA_BF16(acc[0][nn], ah[0], bh[h*2], bh[h*2+1]);
                    MMA_BF16(acc[0][nn], ah[0], bl[h*2], bl[h*2+1]);
                    MMA_BF16(acc[0][nn], al[0], bh[h*2], bh[h*2+1]);
                    MMA_BF16(acc[1][nn], ah[1], bh[h*2], bh[h*2+1]);
                    MMA_BF16(acc[1][nn], ah[1], bl[h*2], bl[h*2+1]);
                    MMA_BF16(acc[1][nn], al[1], bh[h*2], bh[h*2+1]);
                }
            }
        }

        // expert boundary: fold gated partial into final accumulator
        if (((c + 1) & (ECHUNKS - 1)) == 0) {
            const int e = c >> 7;   // c / ECHUNKS
#pragma unroll
            for (int mf = 0; mf < 2; mf++) {
                const int ra = bm + m0 + mf * 16 + (lane >> 2);
                const float ga = gate[ra * E_ + e];
                const float gb = gate[(ra + 8) * E_ + e];
#pragma unroll
                for (int nn = 0; nn < 8; nn++) {
                    accF[mf][nn][0] = fmaf(ga, acc[mf][nn][0], accF[mf][nn][0]);
                    accF[mf][nn][1] = fmaf(ga, acc[mf][nn][1], accF[mf][nn][1]);
                    accF[mf][nn][2] = fmaf(gb, acc[mf][nn][2], accF[mf][nn][2]);
                    accF[mf][nn][3] = fmaf(gb, acc[mf][nn][3], accF[mf][nn][3]);
                    acc[mf][nn][0] = 0.f; acc[mf][nn][1] = 0.f;
                    acc[mf][nn][2] = 0.f; acc[mf][nn][3] = 0.f;
                }
            }
        }
        __syncthreads();
    }

#pragma unroll
    for (int mf = 0; mf < 2; mf++) {
        const int ra = bm + m0 + mf * 16 + (lane >> 2);
        const int rb = ra + 8;
        float g8a[8], g8b[8];
#pragma unroll
        for (int e = 0; e < 8; e++) { g8a[e] = gate[ra * E_ + e]; g8b[e] = gate[rb * E_ + e]; }
#pragma unroll
        for (int nn = 0; nn < 8; nn++) {
            const int gc = bn + n0 + nn * 8 + (lane & 3) * 2;
            float v00 = accF[mf][nn][0], v01 = accF[mf][nn][1];
            float v10 = accF[mf][nn][2], v11 = accF[mf][nn][3];
#pragma unroll
            for (int e = 0; e < 8; e++) {
                const float w0 = eb2[e * OUT_ + gc], w1 = eb2[e * OUT_ + gc + 1];
                v00 = fmaf(g8a[e], w0, v00); v01 = fmaf(g8a[e], w1, v01);
                v10 = fmaf(g8b[e], w0, v10); v11 = fmaf(g8b[e], w1, v11);
            }
            *reinterpret_cast<float2*>(&outf[(size_t)ra * OUT_ + gc]) = make_float2(v00, v01);
            *reinterpret_cast<float2*>(&outf[(size_t)rb * OUT_ + gc]) = make_float2(v10, v11);
        }
    }
}

// ===========================================================================
extern "C" void kernel_launch(void* const* d_in, const int* in_sizes, int n_in,
                              void* d_out, int out_size)
{
    const float* x   = (const float*)d_in[0];
    const float* gW1 = (const float*)d_in[1];
    const float* gb1 = (const float*)d_in[2];
    const float* gW2 = (const float*)d_in[3];
    const float* gb2 = (const float*)d_in[4];
    const float* eW1 = (const float*)d_in[5];
    const float* eb1 = (const float*)d_in[6];
    const float* eW2 = (const float*)d_in[7];
    const float* eb2 = (const float*)d_in[8];

    float* out  = (float*)d_out;
    float* gout = out + (size_t)B_ * OUT_;

    float *Hg, *probs, *gate;
    __nv_bfloat16 *xhi, *xlo, *w1thi, *w1tlo, *w2thi, *w2tlo, *Hhi, *Hlo;
    cudaGetSymbolAddress((void**)&Hg,    d_Hg);
    cudaGetSymbolAddress((void**)&probs, d_probs);
    cudaGetSymbolAddress((void**)&gate,  d_gate);
    cudaGetSymbolAddress((void**)&xhi,   d_xhi);
    cudaGetSymbolAddress((void**)&xlo,   d_xlo);
    cudaGetSymbolAddress((void**)&w1thi, d_w1thi);
    cudaGetSymbolAddress((void**)&w1tlo, d_w1tlo);
    cudaGetSymbolAddress((void**)&w2thi, d_w2thi);
    cudaGetSymbolAddress((void**)&w2tlo, d_w2tlo);
    cudaGetSymbolAddress((void**)&Hhi,   d_Hhi);
    cudaGetSymbolAddress((void**)&Hlo,   d_Hlo);

    const int SMEM_MMA = 2 * BUFB;   // 81920 B
    cudaFuncSetAttribute(mma_gemm1, cudaFuncAttributeMaxDynamicSharedMemorySize, SMEM_MMA);
    cudaFuncSetAttribute(mma_gemm2, cudaFuncAttributeMaxDynamicSharedMemorySize, SMEM_MMA);

    // ---- fork: branch A (tensor pipe) on g_s2; branch B (fma pipe) on stream 0
    cudaEventRecord(g_evFork, 0);
    cudaStreamWaitEvent(g_s2, g_evFork, 0);

    // branch A: x/eW1 prep + gate-free GEMM1
    split_x<<<(B_ * IN_) / 256, 256, 0, g_s2>>>(x, xhi, xlo, B_ * IN_);
    transpose_split<<<dim3(HID_ / 32, IN_ / 32, E_), dim3(32, 8), 0, g_s2>>>(
        eW1, w1thi, w1tlo, IN_, HID_);
    mma_gemm1<<<dim3(B_ / 128, EH_ / 128), 256, SMEM_MMA, g_s2>>>(
        xhi, xlo, w1thi, w1tlo, eb1, Hhi, Hlo, IN_, IN_ / KCH);
    cudaEventRecord(g_evJoin, g_s2);

    // branch B: w2 prep + gating (value-exact)
    transpose_split<<<dim3(OUT_ / 32, EH_ / 32, 1), dim3(32, 8)>>>(eW2, w2thi, w2tlo, EH_, OUT_);
    hg_gemm<<<dim3(HID_ / 128, B_ / 128), 256>>>(x, gW1, gb1, Hg);
    gating_logits_softmax<<<(B_ * E_) / 256, 256>>>(Hg, gW2, gb2, probs);
    gating_scan<<<1, 256>>>(probs, gate, gout);

    // ---- join, then GEMM2 with per-expert gate folding
    cudaStreamWaitEvent(0, g_evJoin, 0);
    mma_gemm2<<<dim3(B_ / 128, OUT_ / 128), 256, SMEM_MMA>>>(
        Hhi, Hlo, w2thi, w2tlo, eb2, gate, out, EH_, EH_ / KCH);
}

// round 16
// speedup vs baseline: 1.0281x; 1.0281x over previous
#include <cuda_runtime.h>
#include <cuda_bf16.h>
#include <math.h>
#include <stdint.h>

#define B_    4096
#define IN_   1024
#define HID_  4096
#define OUT_  1024
#define E_    8
#define EH_   (E_ * HID_)

#define KCH   32
#define RSB   80
#define TILEB (128 * RSB)
#define BUFB  (4 * TILEB)

// ---------------- scratch ----------------
__device__ float d_Hg[(size_t)B_ * HID_];
__device__ float d_probs[B_ * E_];
__device__ float d_gate[B_ * E_];
__device__ __nv_bfloat16 d_xhi[(size_t)B_ * IN_];
__device__ __nv_bfloat16 d_xlo[(size_t)B_ * IN_];
__device__ __nv_bfloat16 d_w1thi[(size_t)EH_ * IN_];
__device__ __nv_bfloat16 d_w1tlo[(size_t)EH_ * IN_];
__device__ __nv_bfloat16 d_w2thi[(size_t)OUT_ * EH_];
__device__ __nv_bfloat16 d_w2tlo[(size_t)OUT_ * EH_];
__device__ __nv_bfloat16 d_Hhi[(size_t)B_ * EH_];
__device__ __nv_bfloat16 d_Hlo[(size_t)B_ * EH_];

static cudaStream_t g_s2;
static cudaEvent_t  g_evFork, g_evJoin;
static struct GInit {
    GInit() {
        cudaStreamCreateWithFlags(&g_s2, cudaStreamNonBlocking);
        cudaEventCreateWithFlags(&g_evFork, cudaEventDisableTiming);
        cudaEventCreateWithFlags(&g_evJoin, cudaEventDisableTiming);
    }
} g_init;

__device__ __forceinline__ uint32_t smem_u32(const void* p) {
    uint32_t a;
    asm("{ .reg .u64 t; cvta.to.shared.u64 t, %1; cvt.u32.u64 %0, t; }" : "=r"(a) : "l"(p));
    return a;
}
#define LDSM4(r, addr) \
    asm volatile("ldmatrix.sync.aligned.m8n8.x4.shared.b16 {%0,%1,%2,%3}, [%4];" \
        : "=r"((r)[0]), "=r"((r)[1]), "=r"((r)[2]), "=r"((r)[3]) : "r"(addr))
#define MMA_BF16(c, a, b0, b1) \
    asm volatile("mma.sync.aligned.m16n8k16.row.col.f32.bf16.bf16.f32 " \
        "{%0,%1,%2,%3}, {%4,%5,%6,%7}, {%8,%9}, {%0,%1,%2,%3};" \
        : "+f"((c)[0]), "+f"((c)[1]), "+f"((c)[2]), "+f"((c)[3]) \
        : "r"((a)[0]), "r"((a)[1]), "r"((a)[2]), "r"((a)[3]), "r"(b0), "r"(b1))
#define CPA16(dst, src) \
    asm volatile("cp.async.cg.shared.global [%0], [%1], 16;" :: "r"(dst), "l"(src))
#define CPA_COMMIT() asm volatile("cp.async.commit_group;" ::: "memory")
#define CPA_WAIT1()  asm volatile("cp.async.wait_group 1;" ::: "memory")
#define CPA_WAIT0()  asm volatile("cp.async.wait_group 0;" ::: "memory")

__device__ __forceinline__ uint32_t pk(__nv_bfloat16 a, __nv_bfloat16 b) {
    return (uint32_t)__bfloat16_as_ushort(a) | ((uint32_t)__bfloat16_as_ushort(b) << 16);
}

// ===========================================================================
// GATING PATH — value-exact vs reference. DO NOT CHANGE ARITHMETIC ORDER.
// ===========================================================================
__device__ __forceinline__ float xla_expf(float input)
{
    float x = fminf(fmaxf(input, -88.3762626647949f), 88.3762626647950f);
    float fx = floorf(__fadd_rn(__fmul_rn(x, 1.44269504088896341f), 0.5f));
    float tmp = __fmul_rn(0.693359375f, fx);
    float z   = __fmul_rn(-2.12194440e-4f, fx);
    float xr  = __fsub_rn(x, tmp);
    xr = __fsub_rn(xr, z);
    z  = __fmul_rn(xr, xr);
    float y = __fadd_rn(__fmul_rn(xr, 1.9875691500E-4f), 1.3981999507E-3f);
    y = __fadd_rn(__fmul_rn(y, xr), 8.3334519073E-3f);
    y = __fadd_rn(__fmul_rn(y, xr), 4.1665795894E-2f);
    y = __fadd_rn(__fmul_rn(y, xr), 1.6666665459E-1f);
    y = __fadd_rn(__fmul_rn(y, xr), 5.0000001201E-1f);
    y = __fadd_rn(__fmul_rn(y, z), xr);
    y = __fadd_rn(1.0f, y);
    int n = (int)fx;
    float p2n = __int_as_float((n + 127) << 23);
    return fmaxf(__fmul_rn(y, p2n), input);
}

__device__ __forceinline__ void mm_step16_uf(const float (*As)[132], const float (*Bs)[132],
                                             float acc[8][8], int tm, int tn)
{
#pragma unroll
    for (int k = 0; k < 16; k++) {
        float a[8], b[8];
        *(float4*)&a[0] = *(const float4*)&As[k][tm];
        *(float4*)&a[4] = *(const float4*)&As[k][tm + 4];
        *(float4*)&b[0] = *(const float4*)&Bs[k][tn];
        *(float4*)&b[4] = *(const float4*)&Bs[k][tn + 4];
#pragma unroll
        for (int i = 0; i < 8; i++)
#pragma unroll
            for (int j = 0; j < 8; j++) {
                float t = __fmul_rn(a[i], b[j]);
                asm volatile("fma.rn.f32 %0, %1, 0f3F800000, %0;"
                             : "+f"(acc[i][j]) : "f"(t));
            }
    }
}

__global__ void __launch_bounds__(256, 2)
hg_gemm(const float* __restrict__ A, const float* __restrict__ W,
        const float* __restrict__ bias, float* __restrict__ C)
{
    const int bm = blockIdx.y * 128, bn = blockIdx.x * 128, tid = threadIdx.x;
    const int N = HID_, K = IN_;

    __shared__ __align__(16) float As[2][16][132];
    __shared__ __align__(16) float Bs[2][16][132];

    const int a_row = tid >> 2, a_col = (tid & 3) << 2;
    const int b_row = tid >> 5, b_col = (tid & 31) << 2;
    const int tm = (tid >> 4) << 3, tn = (tid & 15) << 3;

    float acc[8][8];
#pragma unroll
    for (int i = 0; i < 8; i++)
#pragma unroll
        for (int j = 0; j < 8; j++) acc[i][j] = 0.f;

    const float* Ab = A + (size_t)bm * K;
    float4 pa0, pa1, pb0, pb1;
    pa0 = *(const float4*)(Ab + (size_t)a_row * K + a_col);
    pa1 = *(const float4*)(Ab + (size_t)(a_row + 64) * K + a_col);
    pb0 = *(const float4*)(W + (size_t)b_row * N + bn + b_col);
    pb1 = *(const float4*)(W + (size_t)(b_row + 8) * N + bn + b_col);

    int buf = 0;
    As[buf][a_col+0][a_row] = pa0.x; As[buf][a_col+1][a_row] = pa0.y;
    As[buf][a_col+2][a_row] = pa0.z; As[buf][a_col+3][a_row] = pa0.w;
    As[buf][a_col+0][a_row+64] = pa1.x; As[buf][a_col+1][a_row+64] = pa1.y;
    As[buf][a_col+2][a_row+64] = pa1.z; As[buf][a_col+3][a_row+64] = pa1.w;
    *(float4*)&Bs[buf][b_row][b_col]   = pb0;
    *(float4*)&Bs[buf][b_row+8][b_col] = pb1;
    __syncthreads();

    for (int kt = 16; kt < K; kt += 16) {
        pa0 = *(const float4*)(Ab + (size_t)a_row * K + kt + a_col);
        pa1 = *(const float4*)(Ab + (size_t)(a_row + 64) * K + kt + a_col);
        pb0 = *(const float4*)(W + (size_t)(kt + b_row) * N + bn + b_col);
        pb1 = *(const float4*)(W + (size_t)(kt + b_row + 8) * N + bn + b_col);
        mm_step16_uf(As[buf], Bs[buf], acc, tm, tn);
        buf ^= 1;
        As[buf][a_col+0][a_row] = pa0.x; As[buf][a_col+1][a_row] = pa0.y;
        As[buf][a_col+2][a_row] = pa0.z; As[buf][a_col+3][a_row] = pa0.w;
        As[buf][a_col+0][a_row+64] = pa1.x; As[buf][a_col+1][a_row+64] = pa1.y;
        As[buf][a_col+2][a_row+64] = pa1.z; As[buf][a_col+3][a_row+64] = pa1.w;
        *(float4*)&Bs[buf][b_row][b_col]   = pb0;
        *(float4*)&Bs[buf][b_row+8][b_col] = pb1;
        __syncthreads();
    }
    mm_step16_uf(As[buf], Bs[buf], acc, tm, tn);

#pragma unroll
    for (int i = 0; i < 8; i++) {
        const int row = bm + tm + i;
        float o[8];
#pragma unroll
        for (int j = 0; j < 8; j++) {
            float v = __fadd_rn(acc[i][j], bias[bn + tn + j]);
            o[j] = fmaxf(v, 0.f);
        }
        *(float4*)&C[(size_t)row * N + bn + tn]     = *(float4*)&o[0];
        *(float4*)&C[(size_t)row * N + bn + tn + 4] = *(float4*)&o[4];
    }
}

__global__ void __launch_bounds__(256)
gating_logits_softmax(const float* __restrict__ Hg, const float* __restrict__ gW2,
                      const float* __restrict__ gb2, float* __restrict__ probs)
{
    const int t = blockIdx.x * blockDim.x + threadIdx.x;
    const int b = t >> 3, e = t & 7;
    const float* h = Hg + (size_t)b * HID_;
    const float* w = gW2 + e;

    float acc = 0.f;
#pragma unroll 8
    for (int k = 0; k < HID_; k++)
        acc = __fadd_rn(acc, __fmul_rn(h[k], w[k * 8]));
    float lg = __fadd_rn(acc, gb2[e]);

    const int lane = threadIdx.x & 31;
    const int base = lane & ~7;
    float l[8];
#pragma unroll
    for (int i = 0; i < 8; i++) l[i] = __shfl_sync(0xffffffffu, lg, base + i);

    float mx = l[0];
#pragma unroll
    for (int i = 1; i < 8; i++) mx = fmaxf(mx, l[i]);
    float ex[8], sum = 0.f;
#pragma unroll
    for (int i = 0; i < 8; i++) {
        ex[i] = xla_expf(__fsub_rn(l[i], mx));
        sum = __fadd_rn(sum, ex[i]);
    }
    probs[t] = __fdiv_rn(ex[e], sum);
}

__global__ void gating_scan(const float* __restrict__ probs,
                            float* __restrict__ gate, float* __restrict__ gout)
{
    __shared__ __align__(16) float sp[1024 * 8];
    __shared__ int s_allzero;
    const int tid = threadIdx.x;

    float rta[8];
#pragma unroll
    for (int e = 0; e < 8; e++) rta[e] = 0.f;
    bool anynz = false;

    for (int c0 = 0; c0 < B_; c0 += 1024) {
        for (int i = tid; i < 2048; i += 256)
            *(float4*)&sp[i * 4] = *(const float4*)&probs[(size_t)c0 * 8 + i * 4];
        __syncthreads();

        if (tid == 0) {
            for (int r = 0; r < 1024; r++) {
                float s[8], rta1[8];
                *(float4*)&s[0] = *(const float4*)&sp[r * 8];
                *(float4*)&s[4] = *(const float4*)&sp[r * 8 + 4];
#pragma unroll
                for (int e = 0; e < 8; e++) rta1[e] = __fadd_rn(rta[e], s[e]);

                float ssum = 0.f;
#pragma unroll
                for (int e = 0; e < 8; e++) ssum = __fadd_rn(ssum, rta1[e]);
                const float thr = __fadd_rn(__fdiv_rn(ssum, 8.0f), 0.1f);

                bool any = false, m[8];
#pragma unroll
                for (int e = 0; e < 8; e++) { m[e] = rta1[e] > thr; any |= m[e]; }

                float mod[8];
#pragma unroll
                for (int e = 0; e < 8; e++) mod[e] = m[e] ? 0.f : s[e];
                float norm = 0.f;
#pragma unroll
                for (int e = 0; e < 8; e++) norm = __fadd_rn(norm, mod[e]);
                const float denom = (norm == 0.f) ? 1.f : norm;
#pragma unroll
                for (int e = 0; e < 8; e++) mod[e] = __fdiv_rn(mod[e], denom);

#pragma unroll
                for (int e = 0; e < 8; e++) {
                    const float rta2 = any ? __fsub_rn(rta1[e], s[e]) : rta1[e];
                    rta[e] = __fadd_rn(rta2, mod[e]);
                }
                anynz |= (norm > 0.f);

                const int row = c0 + r;
                float4 m0 = make_float4(mod[0], mod[1], mod[2], mod[3]);
                float4 m1 = make_float4(mod[4], mod[5], mod[6], mod[7]);
                *(float4*)&gate[(size_t)row * 8]     = m0;
                *(float4*)&gate[(size_t)row * 8 + 4] = m1;
                *(float4*)&gout[(size_t)row * 8]     = m0;
                *(float4*)&gout[(size_t)row * 8 + 4] = m1;
            }
            if (c0 + 1024 >= B_) s_allzero = anynz ? 0 : 1;
        }
        __syncthreads();
    }

    if (s_allzero) {
        for (int i = tid; i < B_ * E_; i += 256) { gate[i] = 1.f / E_; gout[i] = 1.f / E_; }
    }
}

// ===========================================================================
// EXPERT PATH
// ===========================================================================

__global__ void __launch_bounds__(256)
split_x(const float* __restrict__ x, __nv_bfloat16* __restrict__ hi,
        __nv_bfloat16* __restrict__ lo, int n)
{
    int i = blockIdx.x * 256 + threadIdx.x;
    if (i < n) {
        float v = x[i];
        __nv_bfloat16 h = __float2bfloat16(v);
        hi[i] = h;
        lo[i] = __float2bfloat16(v - __bfloat162float(h));
    }
}

__global__ void transpose_split(const float* __restrict__ in,
                                __nv_bfloat16* __restrict__ ohi,
                                __nv_bfloat16* __restrict__ olo, int R, int C)
{
    __shared__ float t[32][33];
    const size_t base = (size_t)blockIdx.z * R * C;
    const int c0 = blockIdx.x * 32, r0 = blockIdx.y * 32;
    const int tx = threadIdx.x, ty = threadIdx.y;
#pragma unroll
    for (int i = 0; i < 32; i += 8)
        t[ty + i][tx] = in[base + (size_t)(r0 + ty + i) * C + c0 + tx];
    __syncthreads();
#pragma unroll
    for (int i = 0; i < 32; i += 8) {
        float v = t[tx][ty + i];
        __nv_bfloat16 h = __float2bfloat16(v);
        size_t o = base + (size_t)(c0 + ty + i) * R + r0 + tx;
        ohi[o] = h;
        olo[o] = __float2bfloat16(v - __bfloat162float(h));
    }
}

// gate_scale: H <- g * (hi + lo), re-split in place. 8 bf16 per thread.
__global__ void __launch_bounds__(256)
gate_scale(__nv_bfloat16* __restrict__ hi, __nv_bfloat16* __restrict__ lo,
           const float* __restrict__ gate)
{
    const size_t i = ((size_t)blockIdx.x * 256 + threadIdx.x) * 8;
    const int row = (int)(i >> 15);                 // / EH_
    const int col = (int)(i & (EH_ - 1));
    const float g = gate[row * E_ + (col >> 12)];

    uint4 uh = *reinterpret_cast<uint4*>(hi + i);
    uint4 ul = *reinterpret_cast<uint4*>(lo + i);
    uint32_t* wh = (uint32_t*)&uh;
    uint32_t* wl = (uint32_t*)&ul;
#pragma unroll
    for (int q = 0; q < 4; q++) {
        __nv_bfloat162 h2 = *reinterpret_cast<__nv_bfloat162*>(&wh[q]);
        __nv_bfloat162 l2 = *reinterpret_cast<__nv_bfloat162*>(&wl[q]);
        float v0 = (__bfloat162float(h2.x) + __bfloat162float(l2.x)) * g;
        float v1 = (__bfloat162float(h2.y) + __bfloat162float(l2.y)) * g;
        __nv_bfloat16 nh0 = __float2bfloat16(v0), nh1 = __float2bfloat16(v1);
        __nv_bfloat16 nl0 = __float2bfloat16(v0 - __bfloat162float(nh0));
        __nv_bfloat16 nl1 = __float2bfloat16(v1 - __bfloat162float(nh1));
        wh[q] = pk(nh0, nh1);
        wl[q] = pk(nl0, nl1);
    }
    *reinterpret_cast<uint4*>(hi + i) = uh;
    *reinterpret_cast<uint4*>(lo + i) = ul;
}

// GEMM1 (no gate): H'hi/lo = split(relu(x@eW1[e] + eb1)). Independent of gating.
__global__ void __launch_bounds__(256, 2)
mma_gemm1(const __nv_bfloat16* __restrict__ Ahi, const __nv_bfloat16* __restrict__ Alo,
          const __nv_bfloat16* __restrict__ Bhi, const __nv_bfloat16* __restrict__ Blo,
          const float* __restrict__ bias,
          __nv_bfloat16* __restrict__ outhi, __nv_bfloat16* __restrict__ outlo,
          int K, int NC)
{
    extern __shared__ char smem[];
    const uint32_t sbase = smem_u32(smem);
    const int tid = threadIdx.x, wid = tid >> 5, lane = tid & 31;
    const int bm = blockIdx.x * 128;
    const int bn = blockIdx.y * 128;
    const int m0 = (wid & 3) * 32;
    const int n0 = (wid >> 2) * 64;

    float acc[2][8][4];
#pragma unroll
    for (int i = 0; i < 2; i++)
#pragma unroll
        for (int j = 0; j < 8; j++)
#pragma unroll
            for (int q = 0; q < 4; q++) acc[i][j][q] = 0.f;

    const int r0 = tid >> 2, q4 = tid & 3;
    const __nv_bfloat16* tiles[4] = { Ahi, Alo, Bhi, Blo };

    auto issue = [&](int c, int buf) {
        const int kc = c * KCH;
#pragma unroll
        for (int j = 0; j < 8; j++) {
            const int tle = j >> 1;
            const int rb  = (tle < 2) ? bm : bn;
            const int r   = ((j & 1) ? 64 : 0) + r0;
            const __nv_bfloat16* src = tiles[tle] + (size_t)(rb + r) * K + kc + q4 * 8;
            const uint32_t dst = sbase + (uint32_t)(buf * BUFB + tle * TILEB + r * RSB + q4 * 16);
            CPA16(dst, src);
        }
        CPA_COMMIT();
    };

    issue(0, 0);

    for (int c = 0; c < NC; c++) {
        const int cur = c & 1;
        if (c + 1 < NC) { issue(c + 1, cur ^ 1); CPA_WAIT1(); }
        else            { CPA_WAIT0(); }
        __syncthreads();

        const uint32_t sA_h = sbase + (uint32_t)(cur * BUFB);
        const uint32_t sA_l = sA_h + TILEB;
        const uint32_t sB_h = sA_h + 2 * TILEB;
        const uint32_t sB_l = sA_h + 3 * TILEB;

#pragma unroll
        for (int ks = 0; ks < KCH / 16; ks++) {
            uint32_t ah[2][4], al[2][4];
            const int ar = lane & 15;
            const int ac = ks * 16 + (lane >> 4) * 8;
#pragma unroll
            for (int mf = 0; mf < 2; mf++) {
                const uint32_t off = (uint32_t)((m0 + mf * 16 + ar) * RSB + ac * 2);
                LDSM4(ah[mf], sA_h + off);
                LDSM4(al[mf], sA_l + off);
            }
            const int br = (lane & 7) + ((lane >> 4) & 1) * 8;
            const int bc = ks * 16 + ((lane >> 3) & 1) * 8;
#pragma unroll
            for (int nf = 0; nf < 4; nf++) {
                uint32_t bh[4], bl[4];
                const uint32_t off = (uint32_t)((n0 + nf * 16 + br) * RSB + bc * 2);
                LDSM4(bh, sB_h + off);
                LDSM4(bl, sB_l + off);
#pragma unroll
                for (int h = 0; h < 2; h++) {
                    const int nn = nf * 2 + h;
                    MMA_BF16(acc[0][nn], ah[0], bh[h*2], bh[h*2+1]);
                    MMA_BF16(acc[0][nn], ah[0], bl[h*2], bl[h*2+1]);
                    MMA_BF16(acc[0][nn], al[0], bh[h*2], bh[h*2+1]);
                    MMA_BF16(acc[1][nn], ah[1], bh[h*2], bh[h*2+1]);
                    MMA_BF16(acc[1][nn], ah[1], bl[h*2], bl[h*2+1]);
                    MMA_BF16(acc[1][nn], al[1], bh[h*2], bh[h*2+1]);
                }
            }
        }
        __syncthreads();
    }

#pragma unroll
    for (int mf = 0; mf < 2; mf++) {
        const int ra = bm + m0 + mf * 16 + (lane >> 2);
        const int rb = ra + 8;
#pragma unroll
        for (int nn = 0; nn < 8; nn++) {
            const int gc = bn + n0 + nn * 8 + (lane & 3) * 2;
            const float b0 = bias[gc], b1 = bias[gc + 1];
            float v00 = fmaxf(acc[mf][nn][0] + b0, 0.f);
            float v01 = fmaxf(acc[mf][nn][1] + b1, 0.f);
            float v10 = fmaxf(acc[mf][nn][2] + b0, 0.f);
            float v11 = fmaxf(acc[mf][nn][3] + b1, 0.f);
            __nv_bfloat16 h00 = __float2bfloat16(v00), h01 = __float2bfloat16(v01);
            __nv_bfloat16 h10 = __float2bfloat16(v10), h11 = __float2bfloat16(v11);
            __nv_bfloat16 l00 = __float2bfloat16(v00 - __bfloat162float(h00));
            __nv_bfloat16 l01 = __float2bfloat16(v01 - __bfloat162float(h01));
            __nv_bfloat16 l10 = __float2bfloat16(v10 - __bfloat162float(h10));
            __nv_bfloat16 l11 = __float2bfloat16(v11 - __bfloat162float(h11));
            *reinterpret_cast<uint32_t*>(&outhi[(size_t)ra * EH_ + gc]) = pk(h00, h01);
            *reinterpret_cast<uint32_t*>(&outhi[(size_t)rb * EH_ + gc]) = pk(h10, h11);
            *reinterpret_cast<uint32_t*>(&outlo[(size_t)ra * EH_ + gc]) = pk(l00, l01);
            *reinterpret_cast<uint32_t*>(&outlo[(size_t)rb * EH_ + gc]) = pk(l10, l11);
        }
    }
}

// GEMM2 (R14-proven): out = H@W2 + sum_e g*eb2. 2 CTA/SM.
__global__ void __launch_bounds__(256, 2)
mma_gemm2(const __nv_bfloat16* __restrict__ Ahi, const __nv_bfloat16* __restrict__ Alo,
          const __nv_bfloat16* __restrict__ Bhi, const __nv_bfloat16* __restrict__ Blo,
          const float* __restrict__ eb2, const float* __restrict__ gate,
          float* __restrict__ outf, int K, int NC)
{
    extern __shared__ char smem[];
    const uint32_t sbase = smem_u32(smem);
    const int tid = threadIdx.x, wid = tid >> 5, lane = tid & 31;
    const int bm = blockIdx.x * 128;
    const int bn = blockIdx.y * 128;
    const int m0 = (wid & 3) * 32;
    const int n0 = (wid >> 2) * 64;

    float acc[2][8][4];
#pragma unroll
    for (int i = 0; i < 2; i++)
#pragma unroll
        for (int j = 0; j < 8; j++)
#pragma unroll
            for (int q = 0; q < 4; q++) acc[i][j][q] = 0.f;

    const int r0 = tid >> 2, q4 = tid & 3;
    const __nv_bfloat16* tiles[4] = { Ahi, Alo, Bhi, Blo };

    auto issue = [&](int c, int buf) {
        const int kc = c * KCH;
#pragma unroll
        for (int j = 0; j < 8; j++) {
            const int tle = j >> 1;
            const int rb  = (tle < 2) ? bm : bn;
            const int r   = ((j & 1) ? 64 : 0) + r0;
            const __nv_bfloat16* src = tiles[tle] + (size_t)(rb + r) * K + kc + q4 * 8;
            const uint32_t dst = sbase + (uint32_t)(buf * BUFB + tle * TILEB + r * RSB + q4 * 16);
            CPA16(dst, src);
        }
        CPA_COMMIT();
    };

    issue(0, 0);

    for (int c = 0; c < NC; c++) {
        const int cur = c & 1;
        if (c + 1 < NC) { issue(c + 1, cur ^ 1); CPA_WAIT1(); }
        else            { CPA_WAIT0(); }
        __syncthreads();

        const uint32_t sA_h = sbase + (uint32_t)(cur * BUFB);
        const uint32_t sA_l = sA_h + TILEB;
        const uint32_t sB_h = sA_h + 2 * TILEB;
        const uint32_t sB_l = sA_h + 3 * TILEB;

#pragma unroll
        for (int ks = 0; ks < KCH / 16; ks++) {
            uint32_t ah[2][4], al[2][4];
            const int ar = lane & 15;
            const int ac = ks * 16 + (lane >> 4) * 8;
#pragma unroll
            for (int mf = 0; mf < 2; mf++) {
                const uint32_t off = (uint32_t)((m0 + mf * 16 + ar) * RSB + ac * 2);
                LDSM4(ah[mf], sA_h + off);
                LDSM4(al[mf], sA_l + off);
            }
            const int br = (lane & 7) + ((lane >> 4) & 1) * 8;
            const int bc = ks * 16 + ((lane >> 3) & 1) * 8;
#pragma unroll
            for (int nf = 0; nf < 4; nf++) {
                uint32_t bh[4], bl[4];
                const uint32_t off = (uint32_t)((n0 + nf * 16 + br) * RSB + bc * 2);
                LDSM4(bh, sB_h + off);
                LDSM4(bl, sB_l + off);
#pragma unroll
                for (int h = 0; h < 2; h++) {
                    const int nn = nf * 2 + h;
                    MMA_BF16(acc[0][nn], ah[0], bh[h*2], bh[h*2+1]);
                    MMA_BF16(acc[0][nn], ah[0], bl[h*2], bl[h*2+1]);
                    MMA_BF16(acc[0][nn], al[0], bh[h*2], bh[h*2+1]);
                    MMA_BF16(acc[1][nn], ah[1], bh[h*2], bh[h*2+1]);
                    MMA_BF16(acc[1][nn], ah[1], bl[h*2], bl[h*2+1]);
                    MMA_BF16(acc[1][nn], al[1], bh[h*2], bh[h*2+1]);
                }
            }
        }
        __syncthreads();
    }

#pragma unroll
    for (int mf = 0; mf < 2; mf++) {
        const int ra = bm + m0 + mf * 16 + (lane >> 2);
        const int rb = ra + 8;
        float g8a[8], g8b[8];
#pragma unroll
        for (int e = 0; e < 8; e++) { g8a[e] = gate[ra * E_ + e]; g8b[e] = gate[rb * E_ + e]; }
#pragma unroll
        for (int nn = 0; nn < 8; nn++) {
            const int gc = bn + n0 + nn * 8 + (lane & 3) * 2;
            float v00 = acc[mf][nn][0], v01 = acc[mf][nn][1];
            float v10 = acc[mf][nn][2], v11 = acc[mf][nn][3];
#pragma unroll
            for (int e = 0; e < 8; e++) {
                const float w0 = eb2[e * OUT_ + gc], w1 = eb2[e * OUT_ + gc + 1];
                v00 = fmaf(g8a[e], w0, v00); v01 = fmaf(g8a[e], w1, v01);
                v10 = fmaf(g8b[e], w0, v10); v11 = fmaf(g8b[e], w1, v11);
            }
            *reinterpret_cast<float2*>(&outf[(size_t)ra * OUT_ + gc]) = make_float2(v00, v01);
            *reinterpret_cast<float2*>(&outf[(size_t)rb * OUT_ + gc]) = make_float2(v10, v11);
        }
    }
}

// ===========================================================================
extern "C" void kernel_launch(void* const* d_in, const int* in_sizes, int n_in,
                              void* d_out, int out_size)
{
    const float* x   = (const float*)d_in[0];
    const float* gW1 = (const float*)d_in[1];
    const float* gb1 = (const float*)d_in[2];
    const float* gW2 = (const float*)d_in[3];
    const float* gb2 = (const float*)d_in[4];
    const float* eW1 = (const float*)d_in[5];
    const float* eb1 = (const float*)d_in[6];
    const float* eW2 = (const float*)d_in[7];
    const float* eb2 = (const float*)d_in[8];

    float* out  = (float*)d_out;
    float* gout = out + (size_t)B_ * OUT_;

    float *Hg, *probs, *gate;
    __nv_bfloat16 *xhi, *xlo, *w1thi, *w1tlo, *w2thi, *w2tlo, *Hhi, *Hlo;
    cudaGetSymbolAddress((void**)&Hg,    d_Hg);
    cudaGetSymbolAddress((void**)&probs, d_probs);
    cudaGetSymbolAddress((void**)&gate,  d_gate);
    cudaGetSymbolAddress((void**)&xhi,   d_xhi);
    cudaGetSymbolAddress((void**)&xlo,   d_xlo);
    cudaGetSymbolAddress((void**)&w1thi, d_w1thi);
    cudaGetSymbolAddress((void**)&w1tlo, d_w1tlo);
    cudaGetSymbolAddress((void**)&w2thi, d_w2thi);
    cudaGetSymbolAddress((void**)&w2tlo, d_w2tlo);
    cudaGetSymbolAddress((void**)&Hhi,   d_Hhi);
    cudaGetSymbolAddress((void**)&Hlo,   d_Hlo);

    const int SMEM_MMA = 2 * BUFB;   // 81920 B
    cudaFuncSetAttribute(mma_gemm1, cudaFuncAttributeMaxDynamicSharedMemorySize, SMEM_MMA);
    cudaFuncSetAttribute(mma_gemm2, cudaFuncAttributeMaxDynamicSharedMemorySize, SMEM_MMA);

    // ---- fork: branch A (tensor) on g_s2; branch B (fma / gating) on stream 0
    cudaEventRecord(g_evFork, 0);
    cudaStreamWaitEvent(g_s2, g_evFork, 0);

    // branch A: prep + gate-free GEMM1
    split_x<<<(B_ * IN_) / 256, 256, 0, g_s2>>>(x, xhi, xlo, B_ * IN_);
    transpose_split<<<dim3(HID_ / 32, IN_ / 32, E_), dim3(32, 8), 0, g_s2>>>(
        eW1, w1thi, w1tlo, IN_, HID_);
    mma_gemm1<<<dim3(B_ / 128, EH_ / 128), 256, SMEM_MMA, g_s2>>>(
        xhi, xlo, w1thi, w1tlo, eb1, Hhi, Hlo, IN_, IN_ / KCH);
    cudaEventRecord(g_evJoin, g_s2);

    // branch B: w2 prep + gating (value-exact)
    transpose_split<<<dim3(OUT_ / 32, EH_ / 32, 1), dim3(32, 8)>>>(eW2, w2thi, w2tlo, EH_, OUT_);
    hg_gemm<<<dim3(HID_ / 128, B_ / 128), 256>>>(x, gW1, gb1, Hg);
    gating_logits_softmax<<<(B_ * E_) / 256, 256>>>(Hg, gW2, gb2, probs);
    gating_scan<<<1, 256>>>(probs, gate, gout);

    // ---- join: apply gate to H, then R14-proven GEMM2
    cudaStreamWaitEvent(0, g_evJoin, 0);
    gate_scale<<<(int)(((size_t)B_ * EH_) / 8 / 256), 256>>>(Hhi, Hlo, gate);
    mma_gemm2<<<dim3(B_ / 128, OUT_ / 128), 256, SMEM_MMA>>>(
        Hhi, Hlo, w2thi, w2tlo, eb2, gate, out, EH_, EH_ / KCH);
}

// round 17
// speedup vs baseline: 1.2840x; 1.2489x over previous
#include <cuda_runtime.h>
#include <cuda_fp16.h>
#include <math.h>
#include <stdint.h>

#define B_    4096
#define IN_   1024
#define HID_  4096
#define OUT_  1024
#define E_    8
#define EH_   (E_ * HID_)

#define KCH   32
#define RSB   80
#define TILEB (128 * RSB)
#define BUF3  (3 * TILEB)        // Ahi, Alo, Bhi = 30720 B per k-chunk buffer

// ---------------- scratch ----------------
__device__ float d_Hg[(size_t)B_ * HID_];
__device__ float d_probs[B_ * E_];
__device__ float d_gate[B_ * E_];
__device__ __half d_xhi[(size_t)B_ * IN_];
__device__ __half d_xlo[(size_t)B_ * IN_];
__device__ __half d_w1t[(size_t)EH_ * IN_];
__device__ __half d_w2t[(size_t)OUT_ * EH_];
__device__ __half d_Hhi[(size_t)B_ * EH_];
__device__ __half d_Hlo[(size_t)B_ * EH_];

__device__ __forceinline__ uint32_t smem_u32(const void* p) {
    uint32_t a;
    asm("{ .reg .u64 t; cvta.to.shared.u64 t, %1; cvt.u32.u64 %0, t; }" : "=r"(a) : "l"(p));
    return a;
}
#define LDSM4(r, addr) \
    asm volatile("ldmatrix.sync.aligned.m8n8.x4.shared.b16 {%0,%1,%2,%3}, [%4];" \
        : "=r"((r)[0]), "=r"((r)[1]), "=r"((r)[2]), "=r"((r)[3]) : "r"(addr))
#define MMA_F16(c, a, b0, b1) \
    asm volatile("mma.sync.aligned.m16n8k16.row.col.f32.f16.f16.f32 " \
        "{%0,%1,%2,%3}, {%4,%5,%6,%7}, {%8,%9}, {%0,%1,%2,%3};" \
        : "+f"((c)[0]), "+f"((c)[1]), "+f"((c)[2]), "+f"((c)[3]) \
        : "r"((a)[0]), "r"((a)[1]), "r"((a)[2]), "r"((a)[3]), "r"(b0), "r"(b1))
#define CPA16(dst, src) \
    asm volatile("cp.async.cg.shared.global [%0], [%1], 16;" :: "r"(dst), "l"(src))
#define CPA_COMMIT() asm volatile("cp.async.commit_group;" ::: "memory")
#define CPA_WAIT1()  asm volatile("cp.async.wait_group 1;" ::: "memory")
#define CPA_WAIT0()  asm volatile("cp.async.wait_group 0;" ::: "memory")

__device__ __forceinline__ uint32_t pkh(__half a, __half b) {
    return (uint32_t)__half_as_ushort(a) | ((uint32_t)__half_as_ushort(b) << 16);
}

// ===========================================================================
// GATING PATH — value-exact vs reference. DO NOT CHANGE ARITHMETIC ORDER.
// ===========================================================================
__device__ __forceinline__ float xla_expf(float input)
{
    float x = fminf(fmaxf(input, -88.3762626647949f), 88.3762626647950f);
    float fx = floorf(__fadd_rn(__fmul_rn(x, 1.44269504088896341f), 0.5f));
    float tmp = __fmul_rn(0.693359375f, fx);
    float z   = __fmul_rn(-2.12194440e-4f, fx);
    float xr  = __fsub_rn(x, tmp);
    xr = __fsub_rn(xr, z);
    z  = __fmul_rn(xr, xr);
    float y = __fadd_rn(__fmul_rn(xr, 1.9875691500E-4f), 1.3981999507E-3f);
    y = __fadd_rn(__fmul_rn(y, xr), 8.3334519073E-3f);
    y = __fadd_rn(__fmul_rn(y, xr), 4.1665795894E-2f);
    y = __fadd_rn(__fmul_rn(y, xr), 1.6666665459E-1f);
    y = __fadd_rn(__fmul_rn(y, xr), 5.0000001201E-1f);
    y = __fadd_rn(__fmul_rn(y, z), xr);
    y = __fadd_rn(1.0f, y);
    int n = (int)fx;
    float p2n = __int_as_float((n + 127) << 23);
    return fmaxf(__fmul_rn(y, p2n), input);
}

__device__ __forceinline__ void mm_step16_uf(const float (*As)[132], const float (*Bs)[132],
                                             float acc[8][8], int tm, int tn)
{
#pragma unroll
    for (int k = 0; k < 16; k++) {
        float a[8], b[8];
        *(float4*)&a[0] = *(const float4*)&As[k][tm];
        *(float4*)&a[4] = *(const float4*)&As[k][tm + 4];
        *(float4*)&b[0] = *(const float4*)&Bs[k][tn];
        *(float4*)&b[4] = *(const float4*)&Bs[k][tn + 4];
#pragma unroll
        for (int i = 0; i < 8; i++)
#pragma unroll
            for (int j = 0; j < 8; j++) {
                float t = __fmul_rn(a[i], b[j]);
                asm volatile("fma.rn.f32 %0, %1, 0f3F800000, %0;"
                             : "+f"(acc[i][j]) : "f"(t));
            }
    }
}

__global__ void __launch_bounds__(256, 2)
hg_gemm(const float* __restrict__ A, const float* __restrict__ W,
        const float* __restrict__ bias, float* __restrict__ C)
{
    const int bm = blockIdx.y * 128, bn = blockIdx.x * 128, tid = threadIdx.x;
    const int N = HID_, K = IN_;

    __shared__ __align__(16) float As[2][16][132];
    __shared__ __align__(16) float Bs[2][16][132];

    const int a_row = tid >> 2, a_col = (tid & 3) << 2;
    const int b_row = tid >> 5, b_col = (tid & 31) << 2;
    const int tm = (tid >> 4) << 3, tn = (tid & 15) << 3;

    float acc[8][8];
#pragma unroll
    for (int i = 0; i < 8; i++)
#pragma unroll
        for (int j = 0; j < 8; j++) acc[i][j] = 0.f;

    const float* Ab = A + (size_t)bm * K;
    float4 pa0, pa1, pb0, pb1;
    pa0 = *(const float4*)(Ab + (size_t)a_row * K + a_col);
    pa1 = *(const float4*)(Ab + (size_t)(a_row + 64) * K + a_col);
    pb0 = *(const float4*)(W + (size_t)b_row * N + bn + b_col);
    pb1 = *(const float4*)(W + (size_t)(b_row + 8) * N + bn + b_col);

    int buf = 0;
    As[buf][a_col+0][a_row] = pa0.x; As[buf][a_col+1][a_row] = pa0.y;
    As[buf][a_col+2][a_row] = pa0.z; As[buf][a_col+3][a_row] = pa0.w;
    As[buf][a_col+0][a_row+64] = pa1.x; As[buf][a_col+1][a_row+64] = pa1.y;
    As[buf][a_col+2][a_row+64] = pa1.z; As[buf][a_col+3][a_row+64] = pa1.w;
    *(float4*)&Bs[buf][b_row][b_col]   = pb0;
    *(float4*)&Bs[buf][b_row+8][b_col] = pb1;
    __syncthreads();

    for (int kt = 16; kt < K; kt += 16) {
        pa0 = *(const float4*)(Ab + (size_t)a_row * K + kt + a_col);
        pa1 = *(const float4*)(Ab + (size_t)(a_row + 64) * K + kt + a_col);
        pb0 = *(const float4*)(W + (size_t)(kt + b_row) * N + bn + b_col);
        pb1 = *(const float4*)(W + (size_t)(kt + b_row + 8) * N + bn + b_col);
        mm_step16_uf(As[buf], Bs[buf], acc, tm, tn);
        buf ^= 1;
        As[buf][a_col+0][a_row] = pa0.x; As[buf][a_col+1][a_row] = pa0.y;
        As[buf][a_col+2][a_row] = pa0.z; As[buf][a_col+3][a_row] = pa0.w;
        As[buf][a_col+0][a_row+64] = pa1.x; As[buf][a_col+1][a_row+64] = pa1.y;
        As[buf][a_col+2][a_row+64] = pa1.z; As[buf][a_col+3][a_row+64] = pa1.w;
        *(float4*)&Bs[buf][b_row][b_col]   = pb0;
        *(float4*)&Bs[buf][b_row+8][b_col] = pb1;
        __syncthreads();
    }
    mm_step16_uf(As[buf], Bs[buf], acc, tm, tn);

#pragma unroll
    for (int i = 0; i < 8; i++) {
        const int row = bm + tm + i;
        float o[8];
#pragma unroll
        for (int j = 0; j < 8; j++) {
            float v = __fadd_rn(acc[i][j], bias[bn + tn + j]);
            o[j] = fmaxf(v, 0.f);
        }
        *(float4*)&C[(size_t)row * N + bn + tn]     = *(float4*)&o[0];
        *(float4*)&C[(size_t)row * N + bn + tn + 4] = *(float4*)&o[4];
    }
}

__global__ void __launch_bounds__(256)
gating_logits_softmax(const float* __restrict__ Hg, const float* __restrict__ gW2,
                      const float* __restrict__ gb2, float* __restrict__ probs)
{
    const int t = blockIdx.x * blockDim.x + threadIdx.x;
    const int b = t >> 3, e = t & 7;
    const float* h = Hg + (size_t)b * HID_;
    const float* w = gW2 + e;

    float acc = 0.f;
#pragma unroll 8
    for (int k = 0; k < HID_; k++)
        acc = __fadd_rn(acc, __fmul_rn(h[k], w[k * 8]));
    float lg = __fadd_rn(acc, gb2[e]);

    const int lane = threadIdx.x & 31;
    const int base = lane & ~7;
    float l[8];
#pragma unroll
    for (int i = 0; i < 8; i++) l[i] = __shfl_sync(0xffffffffu, lg, base + i);

    float mx = l[0];
#pragma unroll
    for (int i = 1; i < 8; i++) mx = fmaxf(mx, l[i]);
    float ex[8], sum = 0.f;
#pragma unroll
    for (int i = 0; i < 8; i++) {
        ex[i] = xla_expf(__fsub_rn(l[i], mx));
        sum = __fadd_rn(sum, ex[i]);
    }
    probs[t] = __fdiv_rn(ex[e], sum);
}

__global__ void gating_scan(const float* __restrict__ probs,
                            float* __restrict__ gate, float* __restrict__ gout)
{
    __shared__ __align__(16) float sp[1024 * 8];
    __shared__ int s_allzero;
    const int tid = threadIdx.x;

    float rta[8];
#pragma unroll
    for (int e = 0; e < 8; e++) rta[e] = 0.f;
    bool anynz = false;

    for (int c0 = 0; c0 < B_; c0 += 1024) {
        for (int i = tid; i < 2048; i += 256)
            *(float4*)&sp[i * 4] = *(const float4*)&probs[(size_t)c0 * 8 + i * 4];
        __syncthreads();

        if (tid == 0) {
            for (int r = 0; r < 1024; r++) {
                float s[8], rta1[8];
                *(float4*)&s[0] = *(const float4*)&sp[r * 8];
                *(float4*)&s[4] = *(const float4*)&sp[r * 8 + 4];
#pragma unroll
                for (int e = 0; e < 8; e++) rta1[e] = __fadd_rn(rta[e], s[e]);

                float ssum = 0.f;
#pragma unroll
                for (int e = 0; e < 8; e++) ssum = __fadd_rn(ssum, rta1[e]);
                const float thr = __fadd_rn(__fdiv_rn(ssum, 8.0f), 0.1f);

                bool any = false, m[8];
#pragma unroll
                for (int e = 0; e < 8; e++) { m[e] = rta1[e] > thr; any |= m[e]; }

                float mod[8];
#pragma unroll
                for (int e = 0; e < 8; e++) mod[e] = m[e] ? 0.f : s[e];
                float norm = 0.f;
#pragma unroll
                for (int e = 0; e < 8; e++) norm = __fadd_rn(norm, mod[e]);
                const float denom = (norm == 0.f) ? 1.f : norm;
#pragma unroll
                for (int e = 0; e < 8; e++) mod[e] = __fdiv_rn(mod[e], denom);

#pragma unroll
                for (int e = 0; e < 8; e++) {
                    const float rta2 = any ? __fsub_rn(rta1[e], s[e]) : rta1[e];
                    rta[e] = __fadd_rn(rta2, mod[e]);
                }
                anynz |= (norm > 0.f);

                const int row = c0 + r;
                float4 m0 = make_float4(mod[0], mod[1], mod[2], mod[3]);
                float4 m1 = make_float4(mod[4], mod[5], mod[6], mod[7]);
                *(float4*)&gate[(size_t)row * 8]     = m0;
                *(float4*)&gate[(size_t)row * 8 + 4] = m1;
                *(float4*)&gout[(size_t)row * 8]     = m0;
                *(float4*)&gout[(size_t)row * 8 + 4] = m1;
            }
            if (c0 + 1024 >= B_) s_allzero = anynz ? 0 : 1;
        }
        __syncthreads();
    }

    if (s_allzero) {
        for (int i = tid; i < B_ * E_; i += 256) { gate[i] = 1.f / E_; gout[i] = 1.f / E_; }
    }
}

// ===========================================================================
// EXPERT PATH — fp16 2-pass split (A = hi+lo exact, B = fp16 hi only).
// Error per GEMM ~ 2^-12/sqrt(3) ≈ 1.4e-4 << 1e-3.
// ===========================================================================

__global__ void __launch_bounds__(256)
split_x(const float* __restrict__ x, __half* __restrict__ hi,
        __half* __restrict__ lo, int n)
{
    int i = blockIdx.x * 256 + threadIdx.x;
    if (i < n) {
        float v = x[i];
        __half h = __float2half_rn(v);
        hi[i] = h;
        lo[i] = __float2half_rn(v - __half2float(h));
    }
}

// in [batch][R][C] fp32 -> out [batch][C][R] fp16 (hi only)
__global__ void transpose_hi(const float* __restrict__ in,
                             __half* __restrict__ ohi, int R, int C)
{
    __shared__ float t[32][33];
    const size_t base = (size_t)blockIdx.z * R * C;
    const int c0 = blockIdx.x * 32, r0 = blockIdx.y * 32;
    const int tx = threadIdx.x, ty = threadIdx.y;   // 32 x 8
#pragma unroll
    for (int i = 0; i < 32; i += 8)
        t[ty + i][tx] = in[base + (size_t)(r0 + ty + i) * C + c0 + tx];
    __syncthreads();
#pragma unroll
    for (int i = 0; i < 32; i += 8)
        ohi[base + (size_t)(c0 + ty + i) * R + r0 + tx] = __float2half_rn(t[tx][ty + i]);
}

// D[128x128] = A[m,k] @ B[n,k]^T; A = fp16 hi+lo (2 mma passes), B = fp16.
// MODE 1: Hhi/Hlo = split( relu(acc + eb1[n]) * gate[m, bn>>12] )
// MODE 2: out     = acc + sum_e gate[m,e]*eb2[e][n]
template<int MODE>
__global__ void __launch_bounds__(256, 2)
mma_gemm(const __half* __restrict__ Ahi, const __half* __restrict__ Alo,
         const __half* __restrict__ Bh,
         const float* __restrict__ bias, const float* __restrict__ gate,
         float* __restrict__ outf,
         __half* __restrict__ outhi, __half* __restrict__ outlo,
         int K, int NC)
{
    extern __shared__ char smem[];
    const uint32_t sbase = smem_u32(smem);
    const int tid = threadIdx.x, wid = tid >> 5, lane = tid & 31;
    const int bm = blockIdx.x * 128;
    const int bn = blockIdx.y * 128;
    const int m0 = (wid & 3) * 32;
    const int n0 = (wid >> 2) * 64;

    float acc[2][8][4];
#pragma unroll
    for (int i = 0; i < 2; i++)
#pragma unroll
        for (int j = 0; j < 8; j++)
#pragma unroll
            for (int q = 0; q < 4; q++) acc[i][j][q] = 0.f;

    const int r0 = tid >> 2, q4 = tid & 3;
    const __half* tiles[3] = { Ahi, Alo, Bh };

    auto issue = [&](int c, int buf) {
        const int kc = c * KCH;
#pragma unroll
        for (int j = 0; j < 6; j++) {
            const int tle = j >> 1;
            const int rb  = (tle < 2) ? bm : bn;
            const int r   = ((j & 1) ? 64 : 0) + r0;
            const __half* src = tiles[tle] + (size_t)(rb + r) * K + kc + q4 * 8;
            const uint32_t dst = sbase + (uint32_t)(buf * BUF3 + tle * TILEB + r * RSB + q4 * 16);
            CPA16(dst, src);
        }
        CPA_COMMIT();
    };

    issue(0, 0);

    for (int c = 0; c < NC; c++) {
        const int cur = c & 1;
        if (c + 1 < NC) { issue(c + 1, cur ^ 1); CPA_WAIT1(); }
        else            { CPA_WAIT0(); }
        __syncthreads();

        const uint32_t sA_h = sbase + (uint32_t)(cur * BUF3);
        const uint32_t sA_l = sA_h + TILEB;
        const uint32_t sB_h = sA_h + 2 * TILEB;

#pragma unroll
        for (int ks = 0; ks < KCH / 16; ks++) {
            uint32_t ah[2][4], al[2][4];
            const int ar = lane & 15;
            const int ac = ks * 16 + (lane >> 4) * 8;
#pragma unroll
            for (int mf = 0; mf < 2; mf++) {
                const uint32_t off = (uint32_t)((m0 + mf * 16 + ar) * RSB + ac * 2);
                LDSM4(ah[mf], sA_h + off);
                LDSM4(al[mf], sA_l + off);
            }
            const int br = (lane & 7) + ((lane >> 4) & 1) * 8;
            const int bc = ks * 16 + ((lane >> 3) & 1) * 8;
#pragma unroll
            for (int nf = 0; nf < 4; nf++) {
                uint32_t bh[4];
                const uint32_t off = (uint32_t)((n0 + nf * 16 + br) * RSB + bc * 2);
                LDSM4(bh, sB_h + off);
#pragma unroll
                for (int h = 0; h < 2; h++) {
                    const int nn = nf * 2 + h;
                    MMA_F16(acc[0][nn], ah[0], bh[h*2], bh[h*2+1]);
                    MMA_F16(acc[0][nn], al[0], bh[h*2], bh[h*2+1]);
                    MMA_F16(acc[1][nn], ah[1], bh[h*2], bh[h*2+1]);
                    MMA_F16(acc[1][nn], al[1], bh[h*2], bh[h*2+1]);
                }
            }
        }
        __syncthreads();
    }

    // ---- epilogue ----
    if (MODE == 1) {
        const int e = bn >> 12;
#pragma unroll
        for (int mf = 0; mf < 2; mf++) {
            const int ra = bm + m0 + mf * 16 + (lane >> 2);
            const int rb = ra + 8;
            const float ga = gate[ra * E_ + e];
            const float gb = gate[rb * E_ + e];
#pragma unroll
            for (int nn = 0; nn < 8; nn++) {
                const int gc = bn + n0 + nn * 8 + (lane & 3) * 2;
                const float b0 = bias[gc], b1 = bias[gc + 1];
                float v00 = fmaxf(acc[mf][nn][0] + b0, 0.f) * ga;
                float v01 = fmaxf(acc[mf][nn][1] + b1, 0.f) * ga;
                float v10 = fmaxf(acc[mf][nn][2] + b0, 0.f) * gb;
                float v11 = fmaxf(acc[mf][nn][3] + b1, 0.f) * gb;
                __half h00 = __float2half_rn(v00), h01 = __float2half_rn(v01);
                __half h10 = __float2half_rn(v10), h11 = __float2half_rn(v11);
                __half l00 = __float2half_rn(v00 - __half2float(h00));
                __half l01 = __float2half_rn(v01 - __half2float(h01));
                __half l10 = __float2half_rn(v10 - __half2float(h10));
                __half l11 = __float2half_rn(v11 - __half2float(h11));
                *reinterpret_cast<uint32_t*>(&outhi[(size_t)ra * EH_ + gc]) = pkh(h00, h01);
                *reinterpret_cast<uint32_t*>(&outhi[(size_t)rb * EH_ + gc]) = pkh(h10, h11);
                *reinterpret_cast<uint32_t*>(&outlo[(size_t)ra * EH_ + gc]) = pkh(l00, l01);
                *reinterpret_cast<uint32_t*>(&outlo[(size_t)rb * EH_ + gc]) = pkh(l10, l11);
            }
        }
    } else {
#pragma unroll
        for (int mf = 0; mf < 2; mf++) {
            const int ra = bm + m0 + mf * 16 + (lane >> 2);
            const int rb = ra + 8;
            float g8a[8], g8b[8];
#pragma unroll
            for (int e = 0; e < 8; e++) { g8a[e] = gate[ra * E_ + e]; g8b[e] = gate[rb * E_ + e]; }
#pragma unroll
            for (int nn = 0; nn < 8; nn++) {
                const int gc = bn + n0 + nn * 8 + (lane & 3) * 2;
                float v00 = acc[mf][nn][0], v01 = acc[mf][nn][1];
                float v10 = acc[mf][nn][2], v11 = acc[mf][nn][3];
#pragma unroll
                for (int e = 0; e < 8; e++) {
                    const float w0 = bias[e * OUT_ + gc], w1 = bias[e * OUT_ + gc + 1];
                    v00 = fmaf(g8a[e], w0, v00); v01 = fmaf(g8a[e], w1, v01);
                    v10 = fmaf(g8b[e], w0, v10); v11 = fmaf(g8b[e], w1, v11);
                }
                *reinterpret_cast<float2*>(&outf[(size_t)ra * OUT_ + gc]) = make_float2(v00, v01);
                *reinterpret_cast<float2*>(&outf[(size_t)rb * OUT_ + gc]) = make_float2(v10, v11);
            }
        }
    }
}

// ===========================================================================
extern "C" void kernel_launch(void* const* d_in, const int* in_sizes, int n_in,
                              void* d_out, int out_size)
{
    const float* x   = (const float*)d_in[0];
    const float* gW1 = (const float*)d_in[1];
    const float* gb1 = (const float*)d_in[2];
    const float* gW2 = (const float*)d_in[3];
    const float* gb2 = (const float*)d_in[4];
    const float* eW1 = (const float*)d_in[5];
    const float* eb1 = (const float*)d_in[6];
    const float* eW2 = (const float*)d_in[7];
    const float* eb2 = (const float*)d_in[8];

    float* out  = (float*)d_out;
    float* gout = out + (size_t)B_ * OUT_;

    float *Hg, *probs, *gate;
    __half *xhi, *xlo, *w1t, *w2t, *Hhi, *Hlo;
    cudaGetSymbolAddress((void**)&Hg,    d_Hg);
    cudaGetSymbolAddress((void**)&probs, d_probs);
    cudaGetSymbolAddress((void**)&gate,  d_gate);
    cudaGetSymbolAddress((void**)&xhi,   d_xhi);
    cudaGetSymbolAddress((void**)&xlo,   d_xlo);
    cudaGetSymbolAddress((void**)&w1t,   d_w1t);
    cudaGetSymbolAddress((void**)&w2t,   d_w2t);
    cudaGetSymbolAddress((void**)&Hhi,   d_Hhi);
    cudaGetSymbolAddress((void**)&Hlo,   d_Hlo);

    const int SMEM_MMA = 2 * BUF3;   // 61440 B
    cudaFuncSetAttribute(mma_gemm<1>, cudaFuncAttributeMaxDynamicSharedMemorySize, SMEM_MMA);
    cudaFuncSetAttribute(mma_gemm<2>, cudaFuncAttributeMaxDynamicSharedMemorySize, SMEM_MMA);

    // ---- gating (value-exact) ----
    hg_gemm<<<dim3(HID_ / 128, B_ / 128), 256>>>(x, gW1, gb1, Hg);
    gating_logits_softmax<<<(B_ * E_) / 256, 256>>>(Hg, gW2, gb2, probs);
    gating_scan<<<1, 256>>>(probs, gate, gout);

    // ---- operand prep (fp16) ----
    split_x<<<(B_ * IN_) / 256, 256>>>(x, xhi, xlo, B_ * IN_);
    transpose_hi<<<dim3(HID_ / 32, IN_ / 32, E_), dim3(32, 8)>>>(eW1, w1t, IN_, HID_);
    transpose_hi<<<dim3(OUT_ / 32, EH_ / 32, 1), dim3(32, 8)>>>(eW2, w2t, EH_, OUT_);

    // ---- expert GEMMs: fp16 2-pass ----
    mma_gemm<1><<<dim3(B_ / 128, EH_ / 128), 256, SMEM_MMA>>>(
        xhi, xlo, w1t, eb1, gate, nullptr, Hhi, Hlo, IN_, IN_ / KCH);
    mma_gemm<2><<<dim3(B_ / 128, OUT_ / 128), 256, SMEM_MMA>>>(
        Hhi, Hlo, w2t, eb2, gate, out, nullptr, nullptr, EH_, EH_ / KCH);
}